// round 9
// baseline (speedup 1.0000x reference)
#include <cuda_runtime.h>
#include <cuda_bf16.h>
#include <cstdint>

// ============================================================================
// 4D circular conv (3^4), implicit GEMM on mma.sync.m16n8k16.bf16, hi/lo
// 3-chain split (rel_err ~1.8e-5).
//
// R9: one CTA = full (b,t,y) tile, M=256 (16z x 16w), 512 threads (16 warps),
// 1 CTA/SM. True cp.async double-buffering (stage p+1, wait 1, compute p) from
// precomputed g_X / g_B images. B staged once per phase serves both z-halves
// (traffic halved vs R6). 36 phases = 9 (i,dy) x 4 ci-chunks of 16.
// A slab: 48 k-rows x 288 m (18-row z halo), m-major, stride 592B (no bank
// conflicts: 20r mod 32 distinct). dz = 32B window offset into the halo.
// ============================================================================

#define A_STRIDE 592      // bytes per k-row (296 bf16; 288 used) -> conflict-free
#define OFF_A_LO 28416    // 48 * 592
#define OFF_B    56832
#define B_STRIDE 112      // bytes per co-row (56 bf16; 48 used) -> conflict-free
#define B_BLK    7168     // 64 * 112
#define BUF_SZ   99840    // OFF_B + 6*B_BLK
#define SMEM_BYTES 199680 // 2 buffers
#define PLX 16777216      // elements per g_X plane (4*64*16^4)
#define POS 65536

__device__ __forceinline__ uint32_t smem_u32(const void* p) {
    uint32_t a;
    asm("{ .reg .u64 t; cvta.to.shared.u64 t, %1; cvt.u32.u64 %0, t; }" : "=r"(a) : "l"(p));
    return a;
}
__device__ __forceinline__ void cp16(uint32_t dst, const void* src) {
    asm volatile("cp.async.cg.shared.global [%0], [%1], 16;"
                 :: "r"(dst), "l"(__cvta_generic_to_global(src)) : "memory");
}
#define CP_COMMIT() asm volatile("cp.async.commit_group;" ::: "memory")
#define CP_WAIT(n)  asm volatile("cp.async.wait_group %0;" :: "n"(n) : "memory")

#define LDSM4(R, ADDR) \
    asm volatile("ldmatrix.sync.aligned.m8n8.x4.shared.b16 {%0,%1,%2,%3}, [%4];" \
        : "=r"((R)[0]), "=r"((R)[1]), "=r"((R)[2]), "=r"((R)[3]) : "r"(ADDR))
#define LDSM4T(R, ADDR) \
    asm volatile("ldmatrix.sync.aligned.m8n8.x4.trans.shared.b16 {%0,%1,%2,%3}, [%4];" \
        : "=r"((R)[0]), "=r"((R)[1]), "=r"((R)[2]), "=r"((R)[3]) : "r"(ADDR))
#define MMA16816(D, A, B0, B1) \
    asm volatile("mma.sync.aligned.m16n8k16.row.col.f32.bf16.bf16.f32 " \
        "{%0,%1,%2,%3}, {%4,%5,%6,%7}, {%8,%9}, {%0,%1,%2,%3};" \
        : "+f"((D)[0]), "+f"((D)[1]), "+f"((D)[2]), "+f"((D)[3]) \
        : "r"((A)[0]), "r"((A)[1]), "r"((A)[2]), "r"((A)[3]), "r"(B0), "r"(B1))

// ---- precomputed images -----------------------------------------------------
__device__ __align__(16) __nv_bfloat16 g_B[216 * 3584];     // [tap,ver,chunk][co][k]
__device__ __align__(16) __nv_bfloat16 g_X[6u * PLX];       // [ver*3+dw][b,ci,t,y,z][w]

__global__ void prep_B(const float* __restrict__ wt) {
    int nb = blockIdx.x;                       // (((i*3+dy)*3+dz)*2+ver)*4+chunk
    int chunk = nb & 3, ver = (nb >> 2) & 1, tap = nb >> 3;
    int dz = tap % 3, dy = (tap / 3) % 3, i = tap / 9;
    for (int e = threadIdx.x; e < 64 * 48; e += blockDim.x) {
        int co = e / 48, k = e - co * 48;      // k = cil*3 + dw
        int cil = k / 3, dw = k - cil * 3;
        int ci = chunk * 16 + cil;
        float w = wt[((i * 64 + co) * 64 + ci) * 27 + dy * 9 + dz * 3 + dw];
        __nv_bfloat16 hb = __float2bfloat16(w);
        __nv_bfloat16 vb = ver ? __float2bfloat16(w - __bfloat162float(hb)) : hb;
        g_B[nb * 3584 + co * 56 + k] = vb;
    }
}

// One thread per z-row (16 w floats): split hi/lo, build 3 w-rotations, store.
__global__ __launch_bounds__(256) void prep_X(const float* __restrict__ x) {
    unsigned idx = blockIdx.x * 256 + threadIdx.x;     // < 1048576
    const float4* src = (const float4*)(x + (size_t)idx * 16);
    float v[16];
    *(float4*)(v)      = src[0];
    *(float4*)(v + 4)  = src[1];
    *(float4*)(v + 8)  = src[2];
    *(float4*)(v + 12) = src[3];
    uint32_t hp[8], lp[8];
#pragma unroll
    for (int j = 0; j < 8; j++) {
        float v0 = v[2 * j], v1 = v[2 * j + 1];
        __nv_bfloat16 h0 = __float2bfloat16(v0), h1 = __float2bfloat16(v1);
        __nv_bfloat16 l0 = __float2bfloat16(v0 - __bfloat162float(h0));
        __nv_bfloat16 l1 = __float2bfloat16(v1 - __bfloat162float(h1));
        hp[j] = (uint32_t)__bfloat16_as_ushort(h0) | ((uint32_t)__bfloat16_as_ushort(h1) << 16);
        lp[j] = (uint32_t)__bfloat16_as_ushort(l0) | ((uint32_t)__bfloat16_as_ushort(l1) << 16);
    }
    uint32_t h0r[8], h2r[8], l0r[8], l2r[8];
#pragma unroll
    for (int j = 0; j < 8; j++) {
        h0r[j] = __byte_perm(hp[(j + 7) & 7], hp[j], 0x5432);
        h2r[j] = __byte_perm(hp[j], hp[(j + 1) & 7], 0x5432);
        l0r[j] = __byte_perm(lp[(j + 7) & 7], lp[j], 0x5432);
        l2r[j] = __byte_perm(lp[j], lp[(j + 1) & 7], 0x5432);
    }
    size_t ro = (size_t)idx * 16;
    uint4* p0 = (uint4*)(g_X + 0 * (size_t)PLX + ro);   // ver0 dw0
    uint4* p1 = (uint4*)(g_X + 1 * (size_t)PLX + ro);   // ver0 dw1
    uint4* p2 = (uint4*)(g_X + 2 * (size_t)PLX + ro);   // ver0 dw2
    uint4* p3 = (uint4*)(g_X + 3 * (size_t)PLX + ro);   // ver1 dw0
    uint4* p4 = (uint4*)(g_X + 4 * (size_t)PLX + ro);   // ver1 dw1
    uint4* p5 = (uint4*)(g_X + 5 * (size_t)PLX + ro);   // ver1 dw2
    p0[0] = make_uint4(h0r[0], h0r[1], h0r[2], h0r[3]);
    p0[1] = make_uint4(h0r[4], h0r[5], h0r[6], h0r[7]);
    p1[0] = make_uint4(hp[0], hp[1], hp[2], hp[3]);
    p1[1] = make_uint4(hp[4], hp[5], hp[6], hp[7]);
    p2[0] = make_uint4(h2r[0], h2r[1], h2r[2], h2r[3]);
    p2[1] = make_uint4(h2r[4], h2r[5], h2r[6], h2r[7]);
    p3[0] = make_uint4(l0r[0], l0r[1], l0r[2], l0r[3]);
    p3[1] = make_uint4(l0r[4], l0r[5], l0r[6], l0r[7]);
    p4[0] = make_uint4(lp[0], lp[1], lp[2], lp[3]);
    p4[1] = make_uint4(lp[4], lp[5], lp[6], lp[7]);
    p5[0] = make_uint4(l2r[0], l2r[1], l2r[2], l2r[3]);
    p5[1] = make_uint4(l2r[4], l2r[5], l2r[6], l2r[7]);
}

// ---- per-phase cp.async staging (issue only; no wait) -----------------------
__device__ __forceinline__ void stage_phase(uint32_t sbuf, int b, int t, int y,
                                            int p, int tid) {
    const int chunk = p & 3;
    const int idy9 = p >> 2;
    const int i = idy9 / 3, dy = idy9 - i * 3;
    const int tt = (t + i + 15) & 15;
    const int yy = (y + dy + 15) & 15;
    // A: 48 k-rows x 18 halo-z rows (full 16z + wrap), hi+lo
    const size_t cb = ((size_t)(b * 64 + chunk * 16) << 16) + tt * 4096 + yy * 256;
    for (int idx = tid; idx < 864; idx += 512) {
        int krow = idx / 18, zz = idx - krow * 18;    // krow = cil*3 + dw
        int cil = krow / 3, dw = krow - cil * 3;
        int z_in = (zz + 15) & 15;                    // (zz - 1) mod 16, zz=17 wraps
        size_t so = (size_t)dw * PLX + cb + ((size_t)cil << 16) + z_in * 16;
        uint32_t dst = sbuf + krow * A_STRIDE + zz * 32;
        cp16(dst,      g_X + so);
        cp16(dst + 16, g_X + so + 8);
        cp16(dst + OFF_A_LO,      g_X + 3 * (size_t)PLX + so);
        cp16(dst + OFF_A_LO + 16, g_X + 3 * (size_t)PLX + so + 8);
    }
    // B: 6 blocks x 7168B (slot = dz*2 + ver)
    const int tapb = idy9 * 3;
    for (int q = tid; q < 2688; q += 512) {
        int s = q / 448, r = q - s * 448;
        int dz = s >> 1, ver = s & 1;
        int nb = (((tapb + dz) * 2 + ver) << 2) + chunk;
        cp16(sbuf + OFF_B + s * B_BLK + r * 16,
             (const char*)g_B + (size_t)nb * B_BLK + r * 16);
    }
}

// ---- main kernel ------------------------------------------------------------
__global__ __launch_bounds__(512, 1) void conv4d_mma(
    const float* __restrict__ bias, float* __restrict__ out)
{
    extern __shared__ __align__(16) char smem[];
    const uint32_t sb = smem_u32(smem);
    const int tid = threadIdx.x;
    const int l = tid & 31, wid = tid >> 5;
    const int wm = wid & 7, wn = wid >> 3;     // warp tile: (wm*32 M, wn*32 N)

    const int bid = blockIdx.x;                // 1024 = (b,t,y)
    const int y = bid & 15;
    const int t = (bid >> 4) & 15;
    const int b = bid >> 8;

    const uint32_t aoff = ((l & 7) + ((l >> 4) & 1) * 8) * A_STRIDE + ((l >> 3) & 1) * 16;
    const uint32_t boff = ((l & 7) + ((l >> 4) & 1) * 8) * B_STRIDE + ((l >> 3) & 1) * 16;

    float d[2][4][4];
#pragma unroll
    for (int mi = 0; mi < 2; mi++)
#pragma unroll
        for (int nj = 0; nj < 4; nj++)
#pragma unroll
            for (int e = 0; e < 4; e++) d[mi][nj][e] = 0.f;

    stage_phase(sb, b, t, y, 0, tid);
    CP_COMMIT();

#pragma unroll 1
    for (int p = 0; p < 36; p++) {
        if (p < 35) {
            stage_phase(sb + ((p + 1) & 1) * BUF_SZ, b, t, y, p + 1, tid);
            CP_COMMIT();
            CP_WAIT(1);
        } else {
            CP_WAIT(0);
        }
        __syncthreads();                       // phase-p data visible everywhere

        const uint32_t cbuf = sb + (p & 1) * BUF_SZ;
#pragma unroll 1
        for (int ks = 0; ks < 3; ks++) {
#pragma unroll
            for (int dz = 0; dz < 3; dz++) {
                uint32_t ah[2][4], al[2][4], bhv[2][4], blv[2][4];
                uint32_t ab = cbuf + ks * (16 * A_STRIDE) + dz * 32 + wm * 64 + aoff;
                LDSM4T(ah[0], ab);
                LDSM4T(ah[1], ab + 32);
                LDSM4T(al[0], ab + OFF_A_LO);
                LDSM4T(al[1], ab + OFF_A_LO + 32);
                uint32_t bb = cbuf + OFF_B + (dz * 2) * B_BLK + (wn * 32) * B_STRIDE
                            + ks * 32 + boff;
                LDSM4(bhv[0], bb);
                LDSM4(bhv[1], bb + 16 * B_STRIDE);
                LDSM4(blv[0], bb + B_BLK);
                LDSM4(blv[1], bb + B_BLK + 16 * B_STRIDE);
#pragma unroll
                for (int mi = 0; mi < 2; mi++)
#pragma unroll
                    for (int nj = 0; nj < 4; nj++) {
                        uint32_t* bp = &bhv[nj >> 1][(nj & 1) * 2];
                        uint32_t* lq = &blv[nj >> 1][(nj & 1) * 2];
                        MMA16816(d[mi][nj], ah[mi], bp[0], bp[1]);   // hi*hi
                        MMA16816(d[mi][nj], ah[mi], lq[0], lq[1]);   // hi*lo
                        MMA16816(d[mi][nj], al[mi], bp[0], bp[1]);   // lo*hi
                    }
            }
        }
        __syncthreads();                       // done reading buf before p+2 overwrites
    }

    // ---- epilogue: transpose through SMEM, coalesced float4 stores ----
    float* sf = (float*)smem;                  // [co][260] f32
#pragma unroll
    for (int mi = 0; mi < 2; mi++)
#pragma unroll
        for (int nj = 0; nj < 4; nj++) {
            int r = l >> 2, c = (l & 3) * 2;
            int m0 = wm * 32 + mi * 16;
            int co = wn * 32 + nj * 8 + c;
            sf[co * 260 + m0 + r]           = d[mi][nj][0];
            sf[(co + 1) * 260 + m0 + r]     = d[mi][nj][1];
            sf[co * 260 + m0 + r + 8]       = d[mi][nj][2];
            sf[(co + 1) * 260 + m0 + r + 8] = d[mi][nj][3];
        }
    __syncthreads();
    const int pbase = (t * 16 + y) * 256;
    for (int q = tid; q < 4096; q += 512) {
        int co = q >> 6, c = (q & 63) * 4;
        float4 v = *(float4*)&sf[co * 260 + c];
        float bv = __ldg(bias + co);
        v.x += bv; v.y += bv; v.z += bv; v.w += bv;
        *(float4*)(out + (((size_t)(b * 64 + co)) << 16) + pbase + c) = v;
    }
}

extern "C" void kernel_launch(void* const* d_in, const int* in_sizes, int n_in,
                              void* d_out, int out_size) {
    const float* x    = (const float*)d_in[0];
    const float* wt   = (const float*)d_in[1];
    const float* bias = (const float*)d_in[2];
    float* out        = (float*)d_out;

    cudaFuncSetAttribute(conv4d_mma, cudaFuncAttributeMaxDynamicSharedMemorySize, SMEM_BYTES);
    prep_B<<<216, 256>>>(wt);
    prep_X<<<4096, 256>>>(x);
    conv4d_mma<<<1024, 512, SMEM_BYTES>>>(bias, out);
}

// round 10
// speedup vs baseline: 2.4876x; 2.4876x over previous
#include <cuda_runtime.h>
#include <cuda_fp16.h>
#include <cstdint>

// ============================================================================
// 4D circular conv (3^4), implicit GEMM on mma.sync.m16n8k16.f32.f16.f16.f32,
// SINGLE fp16 chain (10-bit mantissa -> predicted rel_err ~3.5e-4 < 1e-3).
// 3x fewer MMAs than the bf16 3-chain (R6). SMEM halves -> 2 CTAs/SM AND
// cp.async double buffering together. Staging is copy-only from precomputed
// g_X (3 w-rotation fp16 planes) and g_B images.
//
// Per block (b,t,y,h): D[M=128 pos (8z x 16w), N=64 co] in registers.
// K folds (ci=16, dw=3) -> 48/phase; dz = col offset into z-haloed A slab.
// 36 phases = 9 (i,dy) x 4 ci-chunks of 16.
// A in SMEM m-major [k][m] (ldmatrix.trans), B [co][k] (ldmatrix non-trans).
// ============================================================================

#define A_STRIDE 336      // bytes per k-row (168 f16; 160 used) -> conflict-free
#define OFF_B    16128    // 48 * 336
#define B_STRIDE 112      // bytes per co-row (56 f16; 48 used) -> conflict-free
#define B_BLK    7168     // 64 * 112
#define BUF_SZ   37632    // OFF_B + 3*B_BLK
#define SMEM_BYTES 75264  // 2 buffers
#define PLX 16777216      // elements per g_X plane (4*64*16^4)
#define POS 65536

__device__ __forceinline__ uint32_t smem_u32(const void* p) {
    uint32_t a;
    asm("{ .reg .u64 t; cvta.to.shared.u64 t, %1; cvt.u32.u64 %0, t; }" : "=r"(a) : "l"(p));
    return a;
}
__device__ __forceinline__ void cp16(uint32_t dst, const void* src) {
    asm volatile("cp.async.cg.shared.global [%0], [%1], 16;"
                 :: "r"(dst), "l"(__cvta_generic_to_global(src)) : "memory");
}
#define CP_COMMIT() asm volatile("cp.async.commit_group;" ::: "memory")
#define CP_WAIT(n)  asm volatile("cp.async.wait_group %0;" :: "n"(n) : "memory")

#define LDSM4(R, ADDR) \
    asm volatile("ldmatrix.sync.aligned.m8n8.x4.shared.b16 {%0,%1,%2,%3}, [%4];" \
        : "=r"((R)[0]), "=r"((R)[1]), "=r"((R)[2]), "=r"((R)[3]) : "r"(ADDR))
#define LDSM4T(R, ADDR) \
    asm volatile("ldmatrix.sync.aligned.m8n8.x4.trans.shared.b16 {%0,%1,%2,%3}, [%4];" \
        : "=r"((R)[0]), "=r"((R)[1]), "=r"((R)[2]), "=r"((R)[3]) : "r"(ADDR))
#define MMA16816(D, A, B0, B1) \
    asm volatile("mma.sync.aligned.m16n8k16.row.col.f32.f16.f16.f32 " \
        "{%0,%1,%2,%3}, {%4,%5,%6,%7}, {%8,%9}, {%0,%1,%2,%3};" \
        : "+f"((D)[0]), "+f"((D)[1]), "+f"((D)[2]), "+f"((D)[3]) \
        : "r"((A)[0]), "r"((A)[1]), "r"((A)[2]), "r"((A)[3]), "r"(B0), "r"(B1))

// ---- precomputed images -----------------------------------------------------
__device__ __align__(16) __half g_B[108 * 3584];        // [tap27,chunk4][co][k]
__device__ __align__(16) __half g_X[3u * PLX];          // [dw][b,ci,t,y,z][w]

__global__ void prep_B(const float* __restrict__ wt) {
    int nb = blockIdx.x;                       // ((i*3+dy)*3+dz)*4 + chunk
    int chunk = nb & 3, tap = nb >> 2;
    int dz = tap % 3, dy = (tap / 3) % 3, i = tap / 9;
    for (int e = threadIdx.x; e < 64 * 48; e += blockDim.x) {
        int co = e / 48, k = e - co * 48;      // k = cil*3 + dw
        int cil = k / 3, dw = k - cil * 3;
        int ci = chunk * 16 + cil;
        float w = wt[((i * 64 + co) * 64 + ci) * 27 + dy * 9 + dz * 3 + dw];
        g_B[nb * 3584 + co * 56 + k] = __float2half(w);
    }
}

// One thread per z-row (16 w floats): fp16 convert + 3 w-rotations.
__global__ __launch_bounds__(256) void prep_X(const float* __restrict__ x) {
    unsigned idx = blockIdx.x * 256 + threadIdx.x;     // < 1048576
    const float4* src = (const float4*)(x + (size_t)idx * 16);
    float v[16];
    *(float4*)(v)      = src[0];
    *(float4*)(v + 4)  = src[1];
    *(float4*)(v + 8)  = src[2];
    *(float4*)(v + 12) = src[3];
    uint32_t hp[8];
#pragma unroll
    for (int j = 0; j < 8; j++) {
        __half h0 = __float2half(v[2 * j]), h1 = __float2half(v[2 * j + 1]);
        hp[j] = (uint32_t)__half_as_ushort(h0) | ((uint32_t)__half_as_ushort(h1) << 16);
    }
    uint32_t h0r[8], h2r[8];
#pragma unroll
    for (int j = 0; j < 8; j++) {
        h0r[j] = __byte_perm(hp[(j + 7) & 7], hp[j], 0x5432);   // x[(w-1) mod 16]
        h2r[j] = __byte_perm(hp[j], hp[(j + 1) & 7], 0x5432);   // x[(w+1) mod 16]
    }
    size_t ro = (size_t)idx * 16;
    uint4* p0 = (uint4*)(g_X + 0 * (size_t)PLX + ro);   // dw0
    uint4* p1 = (uint4*)(g_X + 1 * (size_t)PLX + ro);   // dw1
    uint4* p2 = (uint4*)(g_X + 2 * (size_t)PLX + ro);   // dw2
    p0[0] = make_uint4(h0r[0], h0r[1], h0r[2], h0r[3]);
    p0[1] = make_uint4(h0r[4], h0r[5], h0r[6], h0r[7]);
    p1[0] = make_uint4(hp[0], hp[1], hp[2], hp[3]);
    p1[1] = make_uint4(hp[4], hp[5], hp[6], hp[7]);
    p2[0] = make_uint4(h2r[0], h2r[1], h2r[2], h2r[3]);
    p2[1] = make_uint4(h2r[4], h2r[5], h2r[6], h2r[7]);
}

// ---- per-phase cp.async staging (issue only; no wait) -----------------------
__device__ __forceinline__ void stage_phase(uint32_t sbuf, int b, int t, int y,
                                            int h, int p, int tid) {
    const int chunk = p & 3;
    const int idy9 = p >> 2;
    const int i = idy9 / 3, dy = idy9 - i * 3;
    const int tt = (t + i + 15) & 15;
    const int yy = (y + dy + 15) & 15;
    // A: 48 k-rows x 10 halo-z rows, 32B each
    const size_t cb = ((size_t)(b * 64 + chunk * 16) << 16) + tt * 4096 + yy * 256;
    for (int idx = tid; idx < 480; idx += 256) {
        int krow = idx / 10, r0 = idx - krow * 10;    // krow = cil*3 + dw
        int cil = krow / 3, dw = krow - cil * 3;
        int z_in = (8 * h + 15 + r0) & 15;
        size_t so = (size_t)dw * PLX + cb + ((size_t)cil << 16) + z_in * 16;
        uint32_t dst = sbuf + krow * A_STRIDE + r0 * 32;
        cp16(dst,      g_X + so);
        cp16(dst + 16, g_X + so + 8);
    }
    // B: 3 dz blocks x 7168B
    const int tapb = idy9 * 3;
    for (int q = tid; q < 1344; q += 256) {
        int s = q / 448, r = q - s * 448;
        int nb = ((tapb + s) << 2) + chunk;
        cp16(sbuf + OFF_B + s * B_BLK + r * 16,
             (const char*)g_B + (size_t)nb * B_BLK + r * 16);
    }
}

// ---- main kernel ------------------------------------------------------------
__global__ __launch_bounds__(256, 2) void conv4d_mma(
    const float* __restrict__ bias, float* __restrict__ out)
{
    extern __shared__ __align__(16) char smem[];
    const uint32_t sb = smem_u32(smem);
    const int tid = threadIdx.x;
    const int l = tid & 31, wid = tid >> 5;
    const int wm = wid & 3, wn = wid >> 2;     // warp tile: (wm*32 M, wn*32 N)

    const int bid = blockIdx.x;
    const int h = bid & 1;
    const int y = (bid >> 1) & 15;
    const int t = (bid >> 5) & 15;
    const int b = bid >> 9;

    const uint32_t aoff = ((l & 7) + ((l >> 4) & 1) * 8) * A_STRIDE + ((l >> 3) & 1) * 16;
    const uint32_t boff = ((l & 7) + ((l >> 4) & 1) * 8) * B_STRIDE + ((l >> 3) & 1) * 16;

    float d[2][4][4];
#pragma unroll
    for (int mi = 0; mi < 2; mi++)
#pragma unroll
        for (int nj = 0; nj < 4; nj++)
#pragma unroll
            for (int e = 0; e < 4; e++) d[mi][nj][e] = 0.f;

    stage_phase(sb, b, t, y, h, 0, tid);
    CP_COMMIT();

#pragma unroll 1
    for (int p = 0; p < 36; p++) {
        if (p < 35) {
            stage_phase(sb + ((p + 1) & 1) * BUF_SZ, b, t, y, h, p + 1, tid);
            CP_COMMIT();
            CP_WAIT(1);
        } else {
            CP_WAIT(0);
        }
        __syncthreads();

        const uint32_t cbuf = sb + (p & 1) * BUF_SZ;
#pragma unroll 1
        for (int ks = 0; ks < 3; ks++) {
#pragma unroll
            for (int dz = 0; dz < 3; dz++) {
                uint32_t a[2][4], bv[2][4];
                uint32_t ab = cbuf + ks * (16 * A_STRIDE) + wm * 64 + dz * 32 + aoff;
                LDSM4T(a[0], ab);
                LDSM4T(a[1], ab + 32);
                uint32_t bb = cbuf + OFF_B + dz * B_BLK + (wn * 32) * B_STRIDE
                            + ks * 32 + boff;
                LDSM4(bv[0], bb);
                LDSM4(bv[1], bb + 16 * B_STRIDE);
#pragma unroll
                for (int mi = 0; mi < 2; mi++)
#pragma unroll
                    for (int nj = 0; nj < 4; nj++) {
                        uint32_t* bp = &bv[nj >> 1][(nj & 1) * 2];
                        MMA16816(d[mi][nj], a[mi], bp[0], bp[1]);
                    }
            }
        }
        __syncthreads();
    }

    // ---- epilogue: transpose through SMEM, coalesced float4 stores ----
    float* sf = (float*)smem;                  // [co][132] f32
#pragma unroll
    for (int mi = 0; mi < 2; mi++)
#pragma unroll
        for (int nj = 0; nj < 4; nj++) {
            int r = l >> 2, c = (l & 3) * 2;
            int m0 = wm * 32 + mi * 16;
            int co = wn * 32 + nj * 8 + c;
            sf[co * 132 + m0 + r]           = d[mi][nj][0];
            sf[(co + 1) * 132 + m0 + r]     = d[mi][nj][1];
            sf[co * 132 + m0 + r + 8]       = d[mi][nj][2];
            sf[(co + 1) * 132 + m0 + r + 8] = d[mi][nj][3];
        }
    __syncthreads();
    const int pbase = (t * 16 + y) * 256 + h * 128;
    for (int q = tid; q < 2048; q += 256) {
        int co = q >> 5, c = (q & 31) * 4;
        float4 v = *(float4*)&sf[co * 132 + c];
        float bv = __ldg(bias + co);
        v.x += bv; v.y += bv; v.z += bv; v.w += bv;
        *(float4*)(out + (((size_t)(b * 64 + co)) << 16) + pbase + c) = v;
    }
}

extern "C" void kernel_launch(void* const* d_in, const int* in_sizes, int n_in,
                              void* d_out, int out_size) {
    const float* x    = (const float*)d_in[0];
    const float* wt   = (const float*)d_in[1];
    const float* bias = (const float*)d_in[2];
    float* out        = (float*)d_out;

    cudaFuncSetAttribute(conv4d_mma, cudaFuncAttributeMaxDynamicSharedMemorySize, SMEM_BYTES);
    prep_B<<<108, 256>>>(wt);
    prep_X<<<4096, 256>>>(x);
    conv4d_mma<<<2048, 256, SMEM_BYTES>>>(bias, out);
}

// round 11
// speedup vs baseline: 2.8099x; 1.1296x over previous
#include <cuda_runtime.h>
#include <cuda_fp16.h>
#include <cstdint>

// ============================================================================
// 4D circular conv (3^4), implicit GEMM on mma.sync.m16n8k16.f32.f16.f16.f32,
// single fp16 chain (rel_err ~2.8e-4). R11: M=256 per block (full 16z x 16w),
// 8 warps x (m32 x n64), 2 CTAs/SM + cp.async double buffering.
// Halves A-ldmatrix & staging traffic vs R10; better MMA issue density.
//
// Per block (b,t,y): D[M=256 pos (16z x 16w), N=64 co] in registers.
// K folds (ci=16, dw=3) -> 48/phase; dz = 32B window offset into z-haloed A.
// 36 phases = 9 (i,dy) x 4 ci-chunks of 16.
// A in SMEM m-major [k][m-halo 288] (ldmatrix.trans), B [co][k] (non-trans).
// ============================================================================

#define A_STRIDE 592      // bytes per k-row (296 f16; 288 used) -> conflict-free
#define OFF_B    28416    // 48 * 592
#define B_STRIDE 112      // bytes per co-row (56 f16; 48 used) -> conflict-free
#define B_BLK    7168     // 64 * 112
#define BUF_SZ   49920    // OFF_B + 3*B_BLK
#define SMEM_BYTES 99840  // 2 buffers
#define PLX 16777216      // elements per g_X plane (4*64*16^4)
#define POS 65536

__device__ __forceinline__ uint32_t smem_u32(const void* p) {
    uint32_t a;
    asm("{ .reg .u64 t; cvta.to.shared.u64 t, %1; cvt.u32.u64 %0, t; }" : "=r"(a) : "l"(p));
    return a;
}
__device__ __forceinline__ void cp16(uint32_t dst, const void* src) {
    asm volatile("cp.async.cg.shared.global [%0], [%1], 16;"
                 :: "r"(dst), "l"(__cvta_generic_to_global(src)) : "memory");
}
#define CP_COMMIT() asm volatile("cp.async.commit_group;" ::: "memory")
#define CP_WAIT(n)  asm volatile("cp.async.wait_group %0;" :: "n"(n) : "memory")

#define LDSM4(R, ADDR) \
    asm volatile("ldmatrix.sync.aligned.m8n8.x4.shared.b16 {%0,%1,%2,%3}, [%4];" \
        : "=r"((R)[0]), "=r"((R)[1]), "=r"((R)[2]), "=r"((R)[3]) : "r"(ADDR))
#define LDSM4T(R, ADDR) \
    asm volatile("ldmatrix.sync.aligned.m8n8.x4.trans.shared.b16 {%0,%1,%2,%3}, [%4];" \
        : "=r"((R)[0]), "=r"((R)[1]), "=r"((R)[2]), "=r"((R)[3]) : "r"(ADDR))
#define MMA16816(D, A, B0, B1) \
    asm volatile("mma.sync.aligned.m16n8k16.row.col.f32.f16.f16.f32 " \
        "{%0,%1,%2,%3}, {%4,%5,%6,%7}, {%8,%9}, {%0,%1,%2,%3};" \
        : "+f"((D)[0]), "+f"((D)[1]), "+f"((D)[2]), "+f"((D)[3]) \
        : "r"((A)[0]), "r"((A)[1]), "r"((A)[2]), "r"((A)[3]), "r"(B0), "r"(B1))

// ---- precomputed images -----------------------------------------------------
__device__ __align__(16) __half g_B[108 * 3584];        // [tap27,chunk4][co][k]
__device__ __align__(16) __half g_X[3u * PLX];          // [dw][b,ci,t,y,z][w]

__global__ void prep_B(const float* __restrict__ wt) {
    int nb = blockIdx.x;                       // ((i*3+dy)*3+dz)*4 + chunk
    int chunk = nb & 3, tap = nb >> 2;
    int dz = tap % 3, dy = (tap / 3) % 3, i = tap / 9;
    for (int e = threadIdx.x; e < 64 * 48; e += blockDim.x) {
        int co = e / 48, k = e - co * 48;      // k = cil*3 + dw
        int cil = k / 3, dw = k - cil * 3;
        int ci = chunk * 16 + cil;
        float w = wt[((i * 64 + co) * 64 + ci) * 27 + dy * 9 + dz * 3 + dw];
        g_B[nb * 3584 + co * 56 + k] = __float2half(w);
    }
}

// One thread per z-row (16 w floats): fp16 convert + 3 w-rotations.
__global__ __launch_bounds__(256) void prep_X(const float* __restrict__ x) {
    unsigned idx = blockIdx.x * 256 + threadIdx.x;     // < 1048576
    const float4* src = (const float4*)(x + (size_t)idx * 16);
    float v[16];
    *(float4*)(v)      = src[0];
    *(float4*)(v + 4)  = src[1];
    *(float4*)(v + 8)  = src[2];
    *(float4*)(v + 12) = src[3];
    uint32_t hp[8];
#pragma unroll
    for (int j = 0; j < 8; j++) {
        __half h0 = __float2half(v[2 * j]), h1 = __float2half(v[2 * j + 1]);
        hp[j] = (uint32_t)__half_as_ushort(h0) | ((uint32_t)__half_as_ushort(h1) << 16);
    }
    uint32_t h0r[8], h2r[8];
#pragma unroll
    for (int j = 0; j < 8; j++) {
        h0r[j] = __byte_perm(hp[(j + 7) & 7], hp[j], 0x5432);   // x[(w-1) mod 16]
        h2r[j] = __byte_perm(hp[j], hp[(j + 1) & 7], 0x5432);   // x[(w+1) mod 16]
    }
    size_t ro = (size_t)idx * 16;
    uint4* p0 = (uint4*)(g_X + 0 * (size_t)PLX + ro);   // dw0
    uint4* p1 = (uint4*)(g_X + 1 * (size_t)PLX + ro);   // dw1
    uint4* p2 = (uint4*)(g_X + 2 * (size_t)PLX + ro);   // dw2
    p0[0] = make_uint4(h0r[0], h0r[1], h0r[2], h0r[3]);
    p0[1] = make_uint4(h0r[4], h0r[5], h0r[6], h0r[7]);
    p1[0] = make_uint4(hp[0], hp[1], hp[2], hp[3]);
    p1[1] = make_uint4(hp[4], hp[5], hp[6], hp[7]);
    p2[0] = make_uint4(h2r[0], h2r[1], h2r[2], h2r[3]);
    p2[1] = make_uint4(h2r[4], h2r[5], h2r[6], h2r[7]);
}

// ---- per-phase cp.async staging (issue only; no wait) -----------------------
__device__ __forceinline__ void stage_phase(uint32_t sbuf, int b, int t, int y,
                                            int p, int tid) {
    const int chunk = p & 3;
    const int idy9 = p >> 2;
    const int i = idy9 / 3, dy = idy9 - i * 3;
    const int tt = (t + i + 15) & 15;
    const int yy = (y + dy + 15) & 15;
    // A: 48 k-rows x 18 halo-z rows (full z + wrap), 32B each
    const size_t cb = ((size_t)(b * 64 + chunk * 16) << 16) + tt * 4096 + yy * 256;
    for (int idx = tid; idx < 864; idx += 256) {
        int krow = idx / 18, zz = idx - krow * 18;    // krow = cil*3 + dw
        int cil = krow / 3, dw = krow - cil * 3;
        int z_in = (zz + 15) & 15;                    // (zz - 1) mod 16
        size_t so = (size_t)dw * PLX + cb + ((size_t)cil << 16) + z_in * 16;
        uint32_t dst = sbuf + krow * A_STRIDE + zz * 32;
        cp16(dst,      g_X + so);
        cp16(dst + 16, g_X + so + 8);
    }
    // B: 3 dz blocks x 7168B
    const int tapb = idy9 * 3;
    for (int q = tid; q < 1344; q += 256) {
        int s = q / 448, r = q - s * 448;
        int nb = ((tapb + s) << 2) + chunk;
        cp16(sbuf + OFF_B + s * B_BLK + r * 16,
             (const char*)g_B + (size_t)nb * B_BLK + r * 16);
    }
}

// ---- main kernel ------------------------------------------------------------
__global__ __launch_bounds__(256, 2) void conv4d_mma(
    const float* __restrict__ bias, float* __restrict__ out)
{
    extern __shared__ __align__(16) char smem[];
    const uint32_t sb = smem_u32(smem);
    const int tid = threadIdx.x;
    const int l = tid & 31, wid = tid >> 5;
    const int wm = wid;                        // warp tile: m = wm*32, full N=64

    const int bid = blockIdx.x;                // 1024 = (b,t,y)
    const int y = bid & 15;
    const int t = (bid >> 4) & 15;
    const int b = bid >> 8;

    const uint32_t aoff = ((l & 7) + ((l >> 4) & 1) * 8) * A_STRIDE + ((l >> 3) & 1) * 16;
    const uint32_t boff = ((l & 7) + ((l >> 4) & 1) * 8) * B_STRIDE + ((l >> 3) & 1) * 16;

    float d[2][8][4];
#pragma unroll
    for (int mi = 0; mi < 2; mi++)
#pragma unroll
        for (int nj = 0; nj < 8; nj++)
#pragma unroll
            for (int e = 0; e < 4; e++) d[mi][nj][e] = 0.f;

    stage_phase(sb, b, t, y, 0, tid);
    CP_COMMIT();

#pragma unroll 1
    for (int p = 0; p < 36; p++) {
        if (p < 35) {
            stage_phase(sb + ((p + 1) & 1) * BUF_SZ, b, t, y, p + 1, tid);
            CP_COMMIT();
            CP_WAIT(1);
        } else {
            CP_WAIT(0);
        }
        __syncthreads();

        const uint32_t cbuf = sb + (p & 1) * BUF_SZ;
#pragma unroll 1
        for (int ks = 0; ks < 3; ks++) {
#pragma unroll
            for (int dz = 0; dz < 3; dz++) {
                uint32_t a[2][4], bv[4][4];
                uint32_t ab = cbuf + ks * (16 * A_STRIDE) + dz * 32 + wm * 64 + aoff;
                LDSM4T(a[0], ab);
                LDSM4T(a[1], ab + 32);
                uint32_t bb = cbuf + OFF_B + dz * B_BLK + ks * 32 + boff;
                LDSM4(bv[0], bb);
                LDSM4(bv[1], bb + 16 * B_STRIDE);
                LDSM4(bv[2], bb + 32 * B_STRIDE);
                LDSM4(bv[3], bb + 48 * B_STRIDE);
#pragma unroll
                for (int mi = 0; mi < 2; mi++)
#pragma unroll
                    for (int nj = 0; nj < 8; nj++) {
                        uint32_t* bp = &bv[nj >> 1][(nj & 1) * 2];
                        MMA16816(d[mi][nj], a[mi], bp[0], bp[1]);
                    }
            }
        }
        __syncthreads();
    }

    // ---- epilogue: transpose through SMEM, coalesced float4 stores ----
    float* sf = (float*)smem;                  // [co][260] f32 = 66560B
#pragma unroll
    for (int mi = 0; mi < 2; mi++)
#pragma unroll
        for (int nj = 0; nj < 8; nj++) {
            int r = l >> 2, c = (l & 3) * 2;
            int m0 = wm * 32 + mi * 16;
            int co = nj * 8 + c;
            sf[co * 260 + m0 + r]           = d[mi][nj][0];
            sf[(co + 1) * 260 + m0 + r]     = d[mi][nj][1];
            sf[co * 260 + m0 + r + 8]       = d[mi][nj][2];
            sf[(co + 1) * 260 + m0 + r + 8] = d[mi][nj][3];
        }
    __syncthreads();
    const int pbase = (t * 16 + y) * 256;
    for (int q = tid; q < 4096; q += 256) {
        int co = q >> 6, c = (q & 63) * 4;
        float4 v = *(float4*)&sf[co * 260 + c];
        float bv = __ldg(bias + co);
        v.x += bv; v.y += bv; v.z += bv; v.w += bv;
        *(float4*)(out + (((size_t)(b * 64 + co)) << 16) + pbase + c) = v;
    }
}

extern "C" void kernel_launch(void* const* d_in, const int* in_sizes, int n_in,
                              void* d_out, int out_size) {
    const float* x    = (const float*)d_in[0];
    const float* wt   = (const float*)d_in[1];
    const float* bias = (const float*)d_in[2];
    float* out        = (float*)d_out;

    cudaFuncSetAttribute(conv4d_mma, cudaFuncAttributeMaxDynamicSharedMemorySize, SMEM_BYTES);
    prep_B<<<108, 256>>>(wt);
    prep_X<<<4096, 256>>>(x);
    conv4d_mma<<<1024, 256, SMEM_BYTES>>>(bias, out);
}

// round 12
// speedup vs baseline: 2.9343x; 1.0443x over previous
#include <cuda_runtime.h>
#include <cuda_fp16.h>
#include <cstdint>

// ============================================================================
// 4D circular conv (3^4), implicit GEMM on mma.sync.m16n8k16.f32.f16.f16.f32,
// single fp16 chain (rel_err ~2.8e-4).
// R12: 4 warps x (m64 x n64) tiles (128 threads, 2 CTAs/SM). Halves SMEM
// crossbar traffic vs R11 (B fragments were 8x-duplicated across warps;
// LDSM:MMA ratio 6:16 -> 8:32), putting the tensor pipe cleanly in charge.
//
// Per block (b,t,y): D[M=256 pos (16z x 16w), N=64 co] in registers.
// K folds (ci=16, dw=3) -> 48/phase; dz = 32B window offset into z-haloed A.
// 36 phases = 9 (i,dy) x 4 ci-chunks of 16; cp.async double-buffered.
// A in SMEM m-major [k][m-halo 288] (ldmatrix.trans), B [co][k] (non-trans).
// ============================================================================

#define A_STRIDE 592      // bytes per k-row (296 f16; 288 used) -> conflict-free
#define OFF_B    28416    // 48 * 592
#define B_STRIDE 112      // bytes per co-row (56 f16; 48 used) -> conflict-free
#define B_BLK    7168     // 64 * 112
#define BUF_SZ   49920    // OFF_B + 3*B_BLK
#define SMEM_BYTES 99840  // 2 buffers
#define PLX 16777216      // elements per g_X plane (4*64*16^4)
#define POS 65536

__device__ __forceinline__ uint32_t smem_u32(const void* p) {
    uint32_t a;
    asm("{ .reg .u64 t; cvta.to.shared.u64 t, %1; cvt.u32.u64 %0, t; }" : "=r"(a) : "l"(p));
    return a;
}
__device__ __forceinline__ void cp16(uint32_t dst, const void* src) {
    asm volatile("cp.async.cg.shared.global [%0], [%1], 16;"
                 :: "r"(dst), "l"(__cvta_generic_to_global(src)) : "memory");
}
#define CP_COMMIT() asm volatile("cp.async.commit_group;" ::: "memory")
#define CP_WAIT(n)  asm volatile("cp.async.wait_group %0;" :: "n"(n) : "memory")

#define LDSM4(R, ADDR) \
    asm volatile("ldmatrix.sync.aligned.m8n8.x4.shared.b16 {%0,%1,%2,%3}, [%4];" \
        : "=r"((R)[0]), "=r"((R)[1]), "=r"((R)[2]), "=r"((R)[3]) : "r"(ADDR))
#define LDSM4T(R, ADDR) \
    asm volatile("ldmatrix.sync.aligned.m8n8.x4.trans.shared.b16 {%0,%1,%2,%3}, [%4];" \
        : "=r"((R)[0]), "=r"((R)[1]), "=r"((R)[2]), "=r"((R)[3]) : "r"(ADDR))
#define MMA16816(D, A, B0, B1) \
    asm volatile("mma.sync.aligned.m16n8k16.row.col.f32.f16.f16.f32 " \
        "{%0,%1,%2,%3}, {%4,%5,%6,%7}, {%8,%9}, {%0,%1,%2,%3};" \
        : "+f"((D)[0]), "+f"((D)[1]), "+f"((D)[2]), "+f"((D)[3]) \
        : "r"((A)[0]), "r"((A)[1]), "r"((A)[2]), "r"((A)[3]), "r"(B0), "r"(B1))

// ---- precomputed images -----------------------------------------------------
__device__ __align__(16) __half g_B[108 * 3584];        // [tap27,chunk4][co][k]
__device__ __align__(16) __half g_X[3u * PLX];          // [dw][b,ci,t,y,z][w]

__global__ void prep_B(const float* __restrict__ wt) {
    int nb = blockIdx.x;                       // ((i*3+dy)*3+dz)*4 + chunk
    int chunk = nb & 3, tap = nb >> 2;
    int dz = tap % 3, dy = (tap / 3) % 3, i = tap / 9;
    for (int e = threadIdx.x; e < 64 * 48; e += blockDim.x) {
        int co = e / 48, k = e - co * 48;      // k = cil*3 + dw
        int cil = k / 3, dw = k - cil * 3;
        int ci = chunk * 16 + cil;
        float w = wt[((i * 64 + co) * 64 + ci) * 27 + dy * 9 + dz * 3 + dw];
        g_B[nb * 3584 + co * 56 + k] = __float2half(w);
    }
}

// One thread per z-row (16 w floats): fp16 convert + 3 w-rotations.
__global__ __launch_bounds__(256) void prep_X(const float* __restrict__ x) {
    unsigned idx = blockIdx.x * 256 + threadIdx.x;     // < 1048576
    const float4* src = (const float4*)(x + (size_t)idx * 16);
    float v[16];
    *(float4*)(v)      = src[0];
    *(float4*)(v + 4)  = src[1];
    *(float4*)(v + 8)  = src[2];
    *(float4*)(v + 12) = src[3];
    uint32_t hp[8];
#pragma unroll
    for (int j = 0; j < 8; j++) {
        __half h0 = __float2half(v[2 * j]), h1 = __float2half(v[2 * j + 1]);
        hp[j] = (uint32_t)__half_as_ushort(h0) | ((uint32_t)__half_as_ushort(h1) << 16);
    }
    uint32_t h0r[8], h2r[8];
#pragma unroll
    for (int j = 0; j < 8; j++) {
        h0r[j] = __byte_perm(hp[(j + 7) & 7], hp[j], 0x5432);   // x[(w-1) mod 16]
        h2r[j] = __byte_perm(hp[j], hp[(j + 1) & 7], 0x5432);   // x[(w+1) mod 16]
    }
    size_t ro = (size_t)idx * 16;
    uint4* p0 = (uint4*)(g_X + 0 * (size_t)PLX + ro);   // dw0
    uint4* p1 = (uint4*)(g_X + 1 * (size_t)PLX + ro);   // dw1
    uint4* p2 = (uint4*)(g_X + 2 * (size_t)PLX + ro);   // dw2
    p0[0] = make_uint4(h0r[0], h0r[1], h0r[2], h0r[3]);
    p0[1] = make_uint4(h0r[4], h0r[5], h0r[6], h0r[7]);
    p1[0] = make_uint4(hp[0], hp[1], hp[2], hp[3]);
    p1[1] = make_uint4(hp[4], hp[5], hp[6], hp[7]);
    p2[0] = make_uint4(h2r[0], h2r[1], h2r[2], h2r[3]);
    p2[1] = make_uint4(h2r[4], h2r[5], h2r[6], h2r[7]);
}

// ---- per-phase cp.async staging (issue only; no wait) -----------------------
__device__ __forceinline__ void stage_phase(uint32_t sbuf, int b, int t, int y,
                                            int p, int tid) {
    const int chunk = p & 3;
    const int idy9 = p >> 2;
    const int i = idy9 / 3, dy = idy9 - i * 3;
    const int tt = (t + i + 15) & 15;
    const int yy = (y + dy + 15) & 15;
    // A: 48 k-rows x 18 halo-z rows (full z + wrap), 32B each
    const size_t cb = ((size_t)(b * 64 + chunk * 16) << 16) + tt * 4096 + yy * 256;
    for (int idx = tid; idx < 864; idx += 128) {
        int krow = idx / 18, zz = idx - krow * 18;    // krow = cil*3 + dw
        int cil = krow / 3, dw = krow - cil * 3;
        int z_in = (zz + 15) & 15;                    // (zz - 1) mod 16
        size_t so = (size_t)dw * PLX + cb + ((size_t)cil << 16) + z_in * 16;
        uint32_t dst = sbuf + krow * A_STRIDE + zz * 32;
        cp16(dst,      g_X + so);
        cp16(dst + 16, g_X + so + 8);
    }
    // B: 3 dz blocks x 7168B
    const int tapb = idy9 * 3;
    for (int q = tid; q < 1344; q += 128) {
        int s = q / 448, r = q - s * 448;
        int nb = ((tapb + s) << 2) + chunk;
        cp16(sbuf + OFF_B + s * B_BLK + r * 16,
             (const char*)g_B + (size_t)nb * B_BLK + r * 16);
    }
}

// ---- main kernel ------------------------------------------------------------
__global__ __launch_bounds__(128, 2) void conv4d_mma(
    const float* __restrict__ bias, float* __restrict__ out)
{
    extern __shared__ __align__(16) char smem[];
    const uint32_t sb = smem_u32(smem);
    const int tid = threadIdx.x;
    const int l = tid & 31, wid = tid >> 5;
    const int wm = wid;                        // warp tile: m = wm*64, full N=64

    const int bid = blockIdx.x;                // 1024 = (b,t,y)
    const int y = bid & 15;
    const int t = (bid >> 4) & 15;
    const int b = bid >> 8;

    const uint32_t aoff = ((l & 7) + ((l >> 4) & 1) * 8) * A_STRIDE + ((l >> 3) & 1) * 16;
    const uint32_t boff = ((l & 7) + ((l >> 4) & 1) * 8) * B_STRIDE + ((l >> 3) & 1) * 16;

    float d[4][8][4];
#pragma unroll
    for (int mi = 0; mi < 4; mi++)
#pragma unroll
        for (int nj = 0; nj < 8; nj++)
#pragma unroll
            for (int e = 0; e < 4; e++) d[mi][nj][e] = 0.f;

    stage_phase(sb, b, t, y, 0, tid);
    CP_COMMIT();

#pragma unroll 1
    for (int p = 0; p < 36; p++) {
        if (p < 35) {
            stage_phase(sb + ((p + 1) & 1) * BUF_SZ, b, t, y, p + 1, tid);
            CP_COMMIT();
            CP_WAIT(1);
        } else {
            CP_WAIT(0);
        }
        __syncthreads();

        const uint32_t cbuf = sb + (p & 1) * BUF_SZ;
#pragma unroll 1
        for (int ks = 0; ks < 3; ks++) {
#pragma unroll
            for (int dz = 0; dz < 3; dz++) {
                uint32_t a[4][4], bv[4][4];
                uint32_t ab = cbuf + ks * (16 * A_STRIDE) + dz * 32 + wm * 128 + aoff;
                LDSM4T(a[0], ab);
                LDSM4T(a[1], ab + 32);
                LDSM4T(a[2], ab + 64);
                LDSM4T(a[3], ab + 96);
                uint32_t bb = cbuf + OFF_B + dz * B_BLK + ks * 32 + boff;
                LDSM4(bv[0], bb);
                LDSM4(bv[1], bb + 16 * B_STRIDE);
                LDSM4(bv[2], bb + 32 * B_STRIDE);
                LDSM4(bv[3], bb + 48 * B_STRIDE);
#pragma unroll
                for (int mi = 0; mi < 4; mi++)
#pragma unroll
                    for (int nj = 0; nj < 8; nj++) {
                        uint32_t* bp = &bv[nj >> 1][(nj & 1) * 2];
                        MMA16816(d[mi][nj], a[mi], bp[0], bp[1]);
                    }
            }
        }
        __syncthreads();
    }

    // ---- epilogue: transpose through SMEM, coalesced float4 stores ----
    float* sf = (float*)smem;                  // [co][260] f32 = 66560B
#pragma unroll
    for (int mi = 0; mi < 4; mi++)
#pragma unroll
        for (int nj = 0; nj < 8; nj++) {
            int r = l >> 2, c = (l & 3) * 2;
            int m0 = wm * 64 + mi * 16;
            int co = nj * 8 + c;
            sf[co * 260 + m0 + r]           = d[mi][nj][0];
            sf[(co + 1) * 260 + m0 + r]     = d[mi][nj][1];
            sf[co * 260 + m0 + r + 8]       = d[mi][nj][2];
            sf[(co + 1) * 260 + m0 + r + 8] = d[mi][nj][3];
        }
    __syncthreads();
    const int pbase = (t * 16 + y) * 256;
    for (int q = tid; q < 4096; q += 128) {
        int co = q >> 6, c = (q & 63) * 4;
        float4 v = *(float4*)&sf[co * 260 + c];
        float bv = __ldg(bias + co);
        v.x += bv; v.y += bv; v.z += bv; v.w += bv;
        *(float4*)(out + (((size_t)(b * 64 + co)) << 16) + pbase + c) = v;
    }
}

extern "C" void kernel_launch(void* const* d_in, const int* in_sizes, int n_in,
                              void* d_out, int out_size) {
    const float* x    = (const float*)d_in[0];
    const float* wt   = (const float*)d_in[1];
    const float* bias = (const float*)d_in[2];
    float* out        = (float*)d_out;

    cudaFuncSetAttribute(conv4d_mma, cudaFuncAttributeMaxDynamicSharedMemorySize, SMEM_BYTES);
    prep_B<<<108, 256>>>(wt);
    prep_X<<<4096, 256>>>(x);
    conv4d_mma<<<1024, 128, SMEM_BYTES>>>(bias, out);
}